// round 1
// baseline (speedup 1.0000x reference)
#include <cuda_runtime.h>

#define N_ENTITY 100000
#define DD 128
#define HIDSZ 256
#define N_REL 48
#define NB 8
#define NEDGE 1000000
#define N_POS 1024
#define CAP (1 << 17)
#define TILE 8

// ---- device scratch (no allocation allowed) ----
__device__ int   g_map[N_ENTITY];            // node id -> canonical position (min pos), else big
__device__ int   g_deg[N_POS * N_REL];       // per (slot, rel) in-degree
__device__ float g_s[N_POS * N_REL * DD];    // raw segment sums (24 MB)
__device__ int4  g_ce[CAP];                  // compacted edges: (src, slot, rel, -)
__device__ int   g_cnt;

// ---- K0: init all scratch ----
__global__ void k_init() {
    int i = blockIdx.x * blockDim.x + threadIdx.x;
    const int total = N_POS * N_REL * DD;  // 6,291,456
    if (i < total) g_s[i] = 0.0f;
    if (i < N_ENTITY) g_map[i] = 0x7fffffff;
    if (i < N_POS * N_REL) g_deg[i] = 0;
    if (i == 0) g_cnt = 0;
}

// ---- K1: scatter entity positions into the map (min pos = canonical) ----
__global__ void k_scatter(const int* __restrict__ ids) {
    int i = blockIdx.x * blockDim.x + threadIdx.x;
    if (i < N_POS) atomicMin(&g_map[ids[i]], i);
}

// ---- K2: scan all edges, compact hits, accumulate per-(slot,rel) degree ----
__global__ void k_filter(const int* __restrict__ ei, const int* __restrict__ et) {
    int e = blockIdx.x * blockDim.x + threadIdx.x;
    if (e >= NEDGE) return;
    int dst = __ldg(&ei[NEDGE + e]);
    int slot = g_map[dst];
    if (slot < N_POS) {
        int rel = __ldg(&et[e]);
        atomicAdd(&g_deg[slot * N_REL + rel], 1);
        int p = atomicAdd(&g_cnt, 1);
        if (p < CAP) g_ce[p] = make_int4(__ldg(&ei[e]), slot, rel, 0);
    }
}

// ---- K3: one warp per compacted edge: s[slot][rel][:] += x[src][:] ----
__global__ void k_accum(const float* __restrict__ x) {
    int warp = (blockIdx.x * blockDim.x + threadIdx.x) >> 5;
    int lane = threadIdx.x & 31;
    int nwarp = (gridDim.x * blockDim.x) >> 5;
    int cnt = min(g_cnt, CAP);
    for (int i = warp; i < cnt; i += nwarp) {
        int4 ce = g_ce[i];
        float4 xv = reinterpret_cast<const float4*>(x + (long)ce.x * DD)[lane];
        float* sp = &g_s[((long)ce.y * N_REL + ce.z) * DD + lane * 4];
        atomicAdd(sp + 0, xv.x);
        atomicAdd(sp + 1, xv.y);
        atomicAdd(sp + 2, xv.z);
        atomicAdd(sp + 3, xv.w);
    }
}

// ---- K4: fused per-position pipeline ----
// block = 256 threads = 2 groups of 128; block handles TILE=8 positions (4 per group).
// smem: xs[8][128] | vv[8][8][128] | wc[8][48*8] | hb[8][128] | zb[8][64] | canon[8]
__global__ __launch_bounds__(256, 2)
void k_final(const float* __restrict__ x, const float* __restrict__ bases,
             const float* __restrict__ comp, const float* __restrict__ root,
             const float* __restrict__ bias,
             const float* __restrict__ w1, const float* __restrict__ b1,
             const float* __restrict__ w2, const float* __restrict__ b2,
             const float* __restrict__ wp, const float* __restrict__ bp,
             const int* __restrict__ ids, float* __restrict__ out) {
    extern __shared__ float sm[];
    float* xs = sm;                       // 1024 floats
    float* vv = xs + TILE * DD;           // 8192
    float* wc = vv + TILE * NB * DD;      // 3072
    float* hb = wc + TILE * N_REL * NB;   // 1024
    float* zb = hb + TILE * DD;           // 512
    int*  canon = (int*)(zb + TILE * 64); // 8 ints

    const int tid = threadIdx.x;
    const int g = tid >> 7;        // 0 or 1
    const int d = tid & 127;
    const int pbase = blockIdx.x * TILE;

    if (tid < TILE) canon[tid] = g_map[ids[pbase + tid]];
    // load node embeddings for the 8 positions
    for (int i = tid; i < TILE * DD; i += 256) {
        int p = i >> 7;
        xs[i] = x[(long)ids[pbase + p] * DD + (i & 127)];
    }
    __syncthreads();

    // per-position relation coefficients: wc[p][rel][k] = comp[rel][k] / max(deg,1)
    for (int i = tid; i < TILE * N_REL * NB; i += 256) {
        int p = i / (N_REL * NB);
        int rk = i % (N_REL * NB);
        int r = rk >> 3, k = rk & 7;
        int dg = g_deg[canon[p] * N_REL + r];
        wc[i] = comp[r * NB + k] * (1.0f / (float)max(dg, 1));
    }
    __syncthreads();

    // phase 2: vv[p][k][d] = sum_rel wc[p][rel][k] * s[canon_p][rel][d]
    for (int p = 0; p < 4; ++p) {
        int pp = g * 4 + p;
        const float* srow = &g_s[(long)canon[pp] * N_REL * DD + d];
        const float* wrow = &wc[pp * N_REL * NB];
        float acc[NB];
#pragma unroll
        for (int k = 0; k < NB; ++k) acc[k] = 0.0f;
        for (int r = 0; r < N_REL; ++r) {
            float sv = srow[r * DD];
#pragma unroll
            for (int k = 0; k < NB; ++k) acc[k] += sv * wrow[r * NB + k];
        }
#pragma unroll
        for (int k = 0; k < NB; ++k) vv[(pp * NB + k) * DD + d] = acc[k];
    }
    __syncthreads();

    // phase 3: rgcn out + residual -> hb
    {
        float acc[4];
#pragma unroll
        for (int p = 0; p < 4; ++p) acc[p] = bias[d];
        for (int j = 0; j < DD; ++j) {
            float r = root[j * DD + d];
#pragma unroll
            for (int p = 0; p < 4; ++p) acc[p] += xs[(g * 4 + p) * DD + j] * r;
        }
#pragma unroll 1
        for (int k = 0; k < NB; ++k) {
            for (int j = 0; j < DD; ++j) {
                float b = bases[((long)k * DD + j) * DD + d];
#pragma unroll
                for (int p = 0; p < 4; ++p) acc[p] += vv[((g * 4 + p) * NB + k) * DD + j] * b;
            }
        }
#pragma unroll
        for (int p = 0; p < 4; ++p)
            hb[(g * 4 + p) * DD + d] = acc[p] + xs[(g * 4 + p) * DD + d];
    }
    __syncthreads();

    // phase 5: zb[p][c] = relu(hb[p] @ w1 + b1)   (8 x 64 outputs)
    for (int t = 0; t < 2; ++t) {
        int i = t * 256 + tid;
        int p = i >> 6, c = i & 63;
        float acc = b1[c];
        for (int j = 0; j < DD; ++j) acc += hb[p * DD + j] * w1[j * 64 + c];
        zb[p * 64 + c] = fmaxf(acc, 0.0f);
    }
    __syncthreads();

    // phase 6: hb[p][d] = zb[p] @ w2 + b2 + hb[p][d]  (in-place, each elem owned by 1 thread)
    for (int t = 0; t < 4; ++t) {
        int i = t * 256 + tid;
        int p = i >> 7, dd2 = i & 127;
        float acc = b2[dd2] + hb[i];
        for (int c = 0; c < 64; ++c) acc += zb[p * 64 + c] * w2[c * DD + dd2];
        hb[i] = acc;
    }
    __syncthreads();

    // phase 7: out[pos][o] = hb[p] @ wp + bp    (8 x 256 outputs)
    {
        int o = tid;  // 0..255
        for (int p = 0; p < TILE; ++p) {
            float acc = bp[o];
            for (int j = 0; j < DD; ++j) acc += hb[p * DD + j] * wp[j * HIDSZ + o];
            out[((long)(pbase + p)) * HIDSZ + o] = acc;
        }
    }
}

extern "C" void kernel_launch(void* const* d_in, const int* in_sizes, int n_in,
                              void* d_out, int out_size) {
    const float* node_embeds = (const float*)d_in[0];
    const float* bases       = (const float*)d_in[1];
    const float* comp        = (const float*)d_in[2];
    const float* root        = (const float*)d_in[3];
    const float* bias        = (const float*)d_in[4];
    const float* w1          = (const float*)d_in[5];
    const float* b1          = (const float*)d_in[6];
    const float* w2          = (const float*)d_in[7];
    const float* b2          = (const float*)d_in[8];
    const float* wp          = (const float*)d_in[9];
    const float* bp          = (const float*)d_in[10];
    const int*   edge_index  = (const int*)d_in[11];
    const int*   edge_type   = (const int*)d_in[12];
    const int*   entity_ids  = (const int*)d_in[13];
    float* out = (float*)d_out;

    // smem for k_final: (1024 + 8192 + 3072 + 1024 + 512) floats + 8 ints
    const int smem_bytes = (TILE * DD + TILE * NB * DD + TILE * N_REL * NB +
                            TILE * DD + TILE * 64) * 4 + TILE * 4;
    static bool attr_set = false;
    cudaFuncSetAttribute(k_final, cudaFuncAttributeMaxDynamicSharedMemorySize, smem_bytes);

    const int total_init = N_POS * N_REL * DD;
    k_init<<<(total_init + 255) / 256, 256>>>();
    k_scatter<<<(N_POS + 255) / 256, 256>>>(entity_ids);
    k_filter<<<(NEDGE + 255) / 256, 256>>>(edge_index, edge_type);
    k_accum<<<512, 128>>>(node_embeds);
    k_final<<<N_POS / TILE, 256, smem_bytes>>>(node_embeds, bases, comp, root, bias,
                                               w1, b1, w2, b2, wp, bp,
                                               entity_ids, out);
    (void)attr_set; (void)in_sizes; (void)n_in; (void)out_size;
}

// round 2
// speedup vs baseline: 1.1130x; 1.1130x over previous
#include <cuda_runtime.h>

#define N_ENTITY 100000
#define DD 128
#define HIDSZ 256
#define N_REL 48
#define NB 8
#define NEDGE 1000000
#define N_POS 1024
#define CAP (1 << 17)
#define TILE 8

// ---- device scratch (no allocation allowed) ----
__device__ int   g_map[N_ENTITY];            // node id -> canonical position (min pos), else big
__device__ int   g_deg[N_POS * N_REL];       // per (slot, rel) in-degree
__device__ float g_s[N_POS * N_REL * DD];    // raw segment sums (only deg>0 rows valid)
__device__ int4  g_ce[CAP];                  // compacted edges: (src, slot, rel, -)
__device__ int   g_cnt;

// ---- K0: init small scratch only (map, deg, cnt) ----
__global__ void k_init0() {
    int i = blockIdx.x * blockDim.x + threadIdx.x;
    if (i < N_ENTITY) g_map[i] = 0x7fffffff;
    if (i < N_POS * N_REL) g_deg[i] = 0;
    if (i == 0) g_cnt = 0;
}

// ---- K1: scatter entity positions into the map (min pos = canonical) ----
__global__ void k_scatter(const int* __restrict__ ids) {
    int i = blockIdx.x * blockDim.x + threadIdx.x;
    if (i < N_POS) atomicMin(&g_map[ids[i]], i);
}

// ---- K2: scan all edges (4/thread), compact hits, accumulate degree ----
__global__ void k_filter(const int* __restrict__ ei, const int* __restrict__ et) {
    int t = blockIdx.x * blockDim.x + threadIdx.x;
    if (t * 4 >= NEDGE) return;
    int4 dst4 = reinterpret_cast<const int4*>(ei + NEDGE)[t];
    int ds[4] = {dst4.x, dst4.y, dst4.z, dst4.w};
#pragma unroll
    for (int q = 0; q < 4; ++q) {
        int e = t * 4 + q;
        int slot = g_map[ds[q]];
        if (slot < N_POS) {
            int rel = __ldg(&et[e]);
            atomicAdd(&g_deg[slot * N_REL + rel], 1);
            int p = atomicAdd(&g_cnt, 1);
            if (p < CAP) g_ce[p] = make_int4(__ldg(&ei[e]), slot, rel, 0);
        }
    }
}

// ---- K2b: zero only the g_s rows that will receive atomic accumulation (deg>=2) ----
__global__ void k_zero() {
    int w = (blockIdx.x * blockDim.x + threadIdx.x) >> 5;
    int lane = threadIdx.x & 31;
    if (w >= N_POS * N_REL) return;
    if (g_deg[w] >= 2) {
        float4 z = make_float4(0.f, 0.f, 0.f, 0.f);
        reinterpret_cast<float4*>(g_s + (size_t)w * DD)[lane] = z;
    }
}

// ---- K3: one warp per compacted edge. deg==1 rows: plain store (no zero/atomic needed) ----
__global__ void k_accum(const float* __restrict__ x) {
    int warp = (blockIdx.x * blockDim.x + threadIdx.x) >> 5;
    int lane = threadIdx.x & 31;
    int nwarp = (gridDim.x * blockDim.x) >> 5;
    int cnt = min(g_cnt, CAP);
    for (int i = warp; i < cnt; i += nwarp) {
        int4 ce = g_ce[i];
        int row = ce.y * N_REL + ce.z;
        int dg = g_deg[row];
        float4 xv = reinterpret_cast<const float4*>(x + (long)ce.x * DD)[lane];
        float* sp = &g_s[(size_t)row * DD + lane * 4];
        if (dg == 1) {
            *reinterpret_cast<float4*>(sp) = xv;
        } else {
            atomicAdd(sp + 0, xv.x);
            atomicAdd(sp + 1, xv.y);
            atomicAdd(sp + 2, xv.z);
            atomicAdd(sp + 3, xv.w);
        }
    }
}

// ---- K4: fused per-position pipeline ----
// block = 256 threads = 2 groups of 128; block handles TILE=8 positions (4 per group).
__global__ __launch_bounds__(256, 2)
void k_final(const float* __restrict__ x, const float* __restrict__ bases,
             const float* __restrict__ comp, const float* __restrict__ root,
             const float* __restrict__ bias,
             const float* __restrict__ w1, const float* __restrict__ b1,
             const float* __restrict__ w2, const float* __restrict__ b2,
             const float* __restrict__ wp, const float* __restrict__ bp,
             const int* __restrict__ ids, float* __restrict__ out) {
    extern __shared__ float sm[];
    float* xs    = sm;                        // 1024
    float* vv    = xs + TILE * DD;            // 8192
    float* compS = vv + TILE * NB * DD;       // 384
    float* normS = compS + N_REL * NB;        // 384  (norm per (pos, rel); 0 => skip)
    float* hb    = normS + TILE * N_REL;      // 1024
    float* zb    = hb + TILE * DD;            // 512
    int*  canon  = (int*)(zb + TILE * 64);    // 8 ints

    const int tid = threadIdx.x;
    const int g = tid >> 7;        // 0 or 1
    const int d = tid & 127;
    const int pbase = blockIdx.x * TILE;

    if (tid < TILE) canon[tid] = g_map[ids[pbase + tid]];
    for (int i = tid; i < TILE * DD; i += 256) {
        int p = i >> 7;
        xs[i] = x[(long)ids[pbase + p] * DD + (i & 127)];
    }
    __syncthreads();

    for (int i = tid; i < N_REL * NB; i += 256) compS[i] = comp[i];
    for (int i = tid; i < TILE * N_REL; i += 256) {
        int p = i / N_REL, r = i % N_REL;
        int dg = g_deg[canon[p] * N_REL + r];
        normS[i] = dg > 0 ? 1.0f / (float)dg : 0.0f;
    }
    __syncthreads();

    // phase 2: vv[p][k][d] = sum_{r: deg>0} norm[p][r] * s[canon_p][r][d] * comp[r][k]
    for (int p = 0; p < 4; ++p) {
        int pp = g * 4 + p;
        const float* srow = &g_s[(size_t)canon[pp] * N_REL * DD + d];
        float acc[NB];
#pragma unroll
        for (int k = 0; k < NB; ++k) acc[k] = 0.0f;
        for (int r = 0; r < N_REL; ++r) {
            float nm = normS[pp * N_REL + r];
            if (nm != 0.0f) {
                float sv = srow[r * DD] * nm;
#pragma unroll
                for (int k = 0; k < NB; ++k) acc[k] += sv * compS[r * NB + k];
            }
        }
#pragma unroll
        for (int k = 0; k < NB; ++k) vv[(pp * NB + k) * DD + d] = acc[k];
    }
    __syncthreads();

    // phase 3: rgcn out + residual -> hb
    {
        float acc[4];
#pragma unroll
        for (int p = 0; p < 4; ++p) acc[p] = bias[d];
        for (int j = 0; j < DD; ++j) {
            float r = root[j * DD + d];
#pragma unroll
            for (int p = 0; p < 4; ++p) acc[p] += xs[(g * 4 + p) * DD + j] * r;
        }
#pragma unroll 1
        for (int k = 0; k < NB; ++k) {
            for (int j = 0; j < DD; ++j) {
                float b = bases[((long)k * DD + j) * DD + d];
#pragma unroll
                for (int p = 0; p < 4; ++p) acc[p] += vv[((g * 4 + p) * NB + k) * DD + j] * b;
            }
        }
#pragma unroll
        for (int p = 0; p < 4; ++p)
            hb[(g * 4 + p) * DD + d] = acc[p] + xs[(g * 4 + p) * DD + d];
    }
    __syncthreads();

    // phase 5: zb[p][c] = relu(hb[p] @ w1 + b1)   (8 x 64 outputs)
    for (int t = 0; t < 2; ++t) {
        int i = t * 256 + tid;
        int p = i >> 6, c = i & 63;
        float acc = b1[c];
        for (int j = 0; j < DD; ++j) acc += hb[p * DD + j] * w1[j * 64 + c];
        zb[p * 64 + c] = fmaxf(acc, 0.0f);
    }
    __syncthreads();

    // phase 6: hb[p][d] = zb[p] @ w2 + b2 + hb[p][d]
    for (int t = 0; t < 4; ++t) {
        int i = t * 256 + tid;
        int p = i >> 7, dd2 = i & 127;
        float acc = b2[dd2] + hb[i];
        for (int c = 0; c < 64; ++c) acc += zb[p * 64 + c] * w2[c * DD + dd2];
        hb[i] = acc;
    }
    __syncthreads();

    // phase 7: out[pos][o] = hb[p] @ wp + bp    (8 x 256 outputs)
    {
        int o = tid;
        for (int p = 0; p < TILE; ++p) {
            float acc = bp[o];
            for (int j = 0; j < DD; ++j) acc += hb[p * DD + j] * wp[j * HIDSZ + o];
            out[((long)(pbase + p)) * HIDSZ + o] = acc;
        }
    }
}

extern "C" void kernel_launch(void* const* d_in, const int* in_sizes, int n_in,
                              void* d_out, int out_size) {
    const float* node_embeds = (const float*)d_in[0];
    const float* bases       = (const float*)d_in[1];
    const float* comp        = (const float*)d_in[2];
    const float* root        = (const float*)d_in[3];
    const float* bias        = (const float*)d_in[4];
    const float* w1          = (const float*)d_in[5];
    const float* b1          = (const float*)d_in[6];
    const float* w2          = (const float*)d_in[7];
    const float* b2          = (const float*)d_in[8];
    const float* wp          = (const float*)d_in[9];
    const float* bp          = (const float*)d_in[10];
    const int*   edge_index  = (const int*)d_in[11];
    const int*   edge_type   = (const int*)d_in[12];
    const int*   entity_ids  = (const int*)d_in[13];
    float* out = (float*)d_out;

    const int smem_bytes = (TILE * DD + TILE * NB * DD + N_REL * NB + TILE * N_REL +
                            TILE * DD + TILE * 64) * 4 + TILE * 4;
    cudaFuncSetAttribute(k_final, cudaFuncAttributeMaxDynamicSharedMemorySize, smem_bytes);

    k_init0<<<(N_ENTITY + 255) / 256, 256>>>();
    k_scatter<<<(N_POS + 255) / 256, 256>>>(entity_ids);
    k_filter<<<(NEDGE / 4 + 255) / 256, 256>>>(edge_index, edge_type);
    k_zero<<<(N_POS * N_REL) / 8, 256>>>();
    k_accum<<<1024, 128>>>(node_embeds);
    k_final<<<N_POS / TILE, 256, smem_bytes>>>(node_embeds, bases, comp, root, bias,
                                               w1, b1, w2, b2, wp, bp,
                                               entity_ids, out);
    (void)in_sizes; (void)n_in; (void)out_size;
}